// round 4
// baseline (speedup 1.0000x reference)
#include <cuda_runtime.h>
#include <math.h>

#define DN 256          // D_NODE == D_GRAPH
#define DL 10           // D_LOGIT
#define MAXB 4096
#define CHUNK 1024
#define NEG_INF (__int_as_float(0xff800000))

// ---------------- device scratch (no allocations allowed) ----------------
__device__ int   g_offsets[MAXB + 1];
__device__ float g_u[MAXB * DL];          // relu(gf) @ W_l1a^T + b_l1
__device__ float g_S[MAXB * DN];          // normalized weighted node sums
__device__ float g_asum[MAXB];            // sum of alpha per graph (1 or 0)
__device__ float g_ctx[MAXB * DN];
__device__ float g_gi[MAXB * 3 * DN];
__device__ float g_gh[MAXB * 3 * DN];

// ---------------- helpers ----------------
__device__ __forceinline__ float leaky(float x) { return x > 0.f ? x : 0.01f * x; }

__device__ __forceinline__ float blockReduceMax(float v, float* sRed) {
    int tid = threadIdx.x, lane = tid & 31, wid = tid >> 5;
#pragma unroll
    for (int o = 16; o > 0; o >>= 1) v = fmaxf(v, __shfl_xor_sync(0xffffffffu, v, o));
    if (lane == 0) sRed[wid] = v;
    __syncthreads();
    if (tid < 32) {
        float t = (lane < 8) ? sRed[lane] : NEG_INF;
#pragma unroll
        for (int o = 4; o > 0; o >>= 1) t = fmaxf(t, __shfl_xor_sync(0xffffffffu, t, o));
        if (lane == 0) sRed[0] = t;
    }
    __syncthreads();
    float r = sRed[0];
    __syncthreads();
    return r;
}

__device__ __forceinline__ float blockReduceSum(float v, float* sRed) {
    int tid = threadIdx.x, lane = tid & 31, wid = tid >> 5;
#pragma unroll
    for (int o = 16; o > 0; o >>= 1) v += __shfl_xor_sync(0xffffffffu, v, o);
    if (lane == 0) sRed[wid] = v;
    __syncthreads();
    if (tid < 32) {
        float t = (lane < 8) ? sRed[lane] : 0.f;
#pragma unroll
        for (int o = 4; o > 0; o >>= 1) t += __shfl_xor_sync(0xffffffffu, t, o);
        if (lane == 0) sRed[0] = t;
    }
    __syncthreads();
    float r = sRed[0];
    __syncthreads();
    return r;
}

__device__ __forceinline__ unsigned f2tf(float f) {
    unsigned u;
    asm("cvt.rna.tf32.f32 %0, %1;" : "=r"(u) : "f"(f));
    return u;
}

__device__ __forceinline__ void mma_tf32(float* c, const unsigned* a, const unsigned* b) {
    asm volatile(
        "mma.sync.aligned.m16n8k8.row.col.f32.tf32.tf32.f32 "
        "{%0,%1,%2,%3},{%4,%5,%6,%7},{%8,%9},{%0,%1,%2,%3};\n"
        : "+f"(c[0]), "+f"(c[1]), "+f"(c[2]), "+f"(c[3])
        : "r"(a[0]), "r"(a[1]), "r"(a[2]), "r"(a[3]), "r"(b[0]), "r"(b[1]));
}

// ---------------- kernel 1: segment offsets ----------------
// segment_ids is sorted. dtype may be int32 (jax without x64) or int64.
// Sniff: if the last odd-indexed int32 word is 0, the data is int64
// (high words of values < 2^31 are all 0). For int32 data the tail segment
// ids are ~B-1 > 0.
__global__ void k_offsets(const void* seg_raw, int N, int B) {
    int i = blockIdx.x * blockDim.x + threadIdx.x;
    if (i >= N) return;
    const int* s32 = (const int*)seg_raw;
    bool is64 = true;
    if (N >= 3) {
        int oi = ((N - 1) & 1) ? (N - 1) : (N - 2);  // odd index near end
        is64 = (s32[oi] == 0);
    }
    int sv, pv;
    if (is64) {
        const long long* s64 = (const long long*)seg_raw;
        sv = (int)s64[i];
        pv = (i == 0) ? -1 : (int)s64[i - 1];
    } else {
        sv = s32[i];
        pv = (i == 0) ? -1 : s32[i - 1];
    }
    for (int g = pv + 1; g <= sv; ++g) g_offsets[g] = i;
    if (i == N - 1) {
        for (int g = sv + 1; g <= B; ++g) g_offsets[g] = N;
    }
}

// ---------------- kernel 2: per-graph u = relu(gf) @ W_l1[:, :256]^T + b_l1 --
__global__ __launch_bounds__(256) void k_u(const float* __restrict__ gf,
                                           const float* __restrict__ W_l1,
                                           const float* __restrict__ b_l1, int B) {
    __shared__ float sW[DL * DN];
    int tid = threadIdx.x;
    for (int idx = tid; idx < DL * DN; idx += 256) {
        int j = idx / DN, c = idx % DN;
        sW[idx] = W_l1[j * (2 * DN) + c];  // first 256 cols (g_bcast part)
    }
    __syncthreads();
    int wid = tid >> 5, lane = tid & 31;
    int g = blockIdx.x * 8 + wid;
    if (g >= B) return;
    float acc[DL];
#pragma unroll
    for (int j = 0; j < DL; j++) acc[j] = 0.f;
    const float4* grow = (const float4*)(gf + (size_t)g * DN);
#pragma unroll
    for (int k2 = 0; k2 < 2; k2++) {
        float4 x = grow[lane + 32 * k2];
        x.x = fmaxf(x.x, 0.f); x.y = fmaxf(x.y, 0.f);
        x.z = fmaxf(x.z, 0.f); x.w = fmaxf(x.w, 0.f);
        int cb = (lane + 32 * k2) * 4;
#pragma unroll
        for (int j = 0; j < DL; j++) {
            float4 w = *(const float4*)&sW[j * DN + cb];
            acc[j] += x.x * w.x + x.y * w.y + x.z * w.z + x.w * w.w;
        }
    }
#pragma unroll
    for (int j = 0; j < DL; j++) {
        float v = acc[j];
#pragma unroll
        for (int o = 16; o > 0; o >>= 1) v += __shfl_xor_sync(0xffffffffu, v, o);
        acc[j] = v;
    }
    if (lane == 0) {
#pragma unroll
        for (int j = 0; j < DL; j++) g_u[g * DL + j] = acc[j] + b_l1[j];
    }
}

// ---------------- kernel 3: main pass (logits + segment softmax + weighted sum)
__global__ __launch_bounds__(256) void k_main(const float* __restrict__ nf,
                                              const float* __restrict__ W_l1,
                                              const float* __restrict__ W_l2,
                                              const float* __restrict__ b_l2) {
    __shared__ float sWb[DL * DN];   // W_l1[:, 256:512]
    __shared__ float sU[DL], sW2[DL];
    __shared__ float sB2;
    __shared__ float sLog[CHUNK];
    __shared__ float sRed[8];

    int tid = threadIdx.x, lane = tid & 31, wid = tid >> 5;
    int g = blockIdx.x;

    for (int idx = tid; idx < DL * DN; idx += 256) {
        int j = idx / DN, c = idx % DN;
        sWb[idx] = W_l1[j * (2 * DN) + DN + c];
    }
    if (tid < DL) { sU[tid] = g_u[g * DL + tid]; sW2[tid] = W_l2[tid]; }
    if (tid == 0) sB2 = b_l2[0];
    int start = g_offsets[g];
    int cnt = g_offsets[g + 1] - start;
    __syncthreads();

    float M = NEG_INF, D = 0.f, Sacc = 0.f;

    for (int base = 0; base < cnt; base += CHUNK) {
        int cn = min(CHUNK, cnt - base);

        // ---- phase 1: logits (warp per node) ----
        for (int n = wid; n < cn; n += 8) {
            const float4* xrow = (const float4*)(nf + (size_t)(start + base + n) * DN);
            float4 x0 = xrow[lane];
            float4 x1 = xrow[lane + 32];
            float acc[DL];
#pragma unroll
            for (int j = 0; j < DL; j++) {
                float4 w0 = *(const float4*)&sWb[j * DN + lane * 4];
                float4 w1 = *(const float4*)&sWb[j * DN + 128 + lane * 4];
                acc[j] = x0.x * w0.x + x0.y * w0.y + x0.z * w0.z + x0.w * w0.w
                       + x1.x * w1.x + x1.y * w1.y + x1.z * w1.z + x1.w * w1.w;
            }
#pragma unroll
            for (int j = 0; j < DL; j++) {
                float v = acc[j];
#pragma unroll
                for (int o = 16; o > 0; o >>= 1) v += __shfl_xor_sync(0xffffffffu, v, o);
                acc[j] = v;
            }
            if (lane == 0) {
                float lg = sB2;
#pragma unroll
                for (int j = 0; j < DL; j++) lg += leaky(acc[j] + sU[j]) * sW2[j];
                sLog[n] = leaky(lg);
            }
        }
        __syncthreads();

        // ---- softmax stats for this chunk (online across chunks) ----
        float lm = NEG_INF;
        for (int n = tid; n < cn; n += 256) lm = fmaxf(lm, sLog[n]);
        float mc = blockReduceMax(lm, sRed);
        float Mn = fmaxf(M, mc);
        float scale = (M == NEG_INF) ? 0.f : __expf(M - Mn);
        float ld = 0.f;
        for (int n = tid; n < cn; n += 256) {
            float w = __expf(sLog[n] - Mn);
            sLog[n] = w;
            ld += w;
        }
        float dc = blockReduceSum(ld, sRed);
        D = D * scale + dc;
        M = Mn;
        __syncthreads();  // all weights in sLog visible

        // ---- phase 2: weighted sum of node rows (thread t owns element t) ----
        Sacc *= scale;
        const float* col = nf + (size_t)(start + base) * DN + tid;
#pragma unroll 4
        for (int n = 0; n < cn; n++) Sacc += sLog[n] * col[(size_t)n * DN];
        __syncthreads();  // before next chunk overwrites sLog
    }

    float inv = 1.f / fmaxf(D, 1e-30f);
    g_S[(size_t)g * DN + tid] = (cnt > 0) ? Sacc * inv : 0.f;
    if (tid == 0) g_asum[g] = (cnt > 0) ? D * inv : 0.f;
}

// ---------------- kernel 4: tf32 GEMM  C[M,N] = A[M,K] @ W[N,K]^T + bias*rs --
#define BM 128
#define BN 64
#define BK 32

__global__ __launch_bounds__(256) void k_gemm(int mode, const float* __restrict__ Aext,
                                              const float* __restrict__ W,
                                              const float* __restrict__ bias,
                                              int M, int N, int K) {
    __shared__ unsigned sA[BM * 36];
    __shared__ unsigned sB[BN * 36];

    const float* A;
    float* C;
    const float* rs = nullptr;
    if (mode == 0)      { A = g_S;   C = g_ctx; rs = g_asum; }
    else if (mode == 1) { A = g_ctx; C = g_gi; }
    else                { A = Aext;  C = g_gh; }

    int tid = threadIdx.x, lane = tid & 31, wid = tid >> 5;
    int nBase = blockIdx.x * BN, mBase = blockIdx.y * BM;
    int warpM = (wid & 3) * 32, warpN = (wid >> 2) * 32;

    float c[2][4][4];
#pragma unroll
    for (int tm = 0; tm < 2; tm++)
#pragma unroll
        for (int tn = 0; tn < 4; tn++)
#pragma unroll
            for (int q = 0; q < 4; q++) c[tm][tn][q] = 0.f;

    for (int kt = 0; kt < K; kt += BK) {
        // stage A tile: 128x32
#pragma unroll
        for (int it = 0; it < 4; it++) {
            int fi = tid + 256 * it;
            int r = fi >> 3, c4 = fi & 7;
            float4 v = *(const float4*)(A + (size_t)(mBase + r) * K + kt + c4 * 4);
            int sa = r * 36 + c4 * 4;
            sA[sa] = f2tf(v.x); sA[sa + 1] = f2tf(v.y);
            sA[sa + 2] = f2tf(v.z); sA[sa + 3] = f2tf(v.w);
        }
        // stage W tile: 64x32
#pragma unroll
        for (int it = 0; it < 2; it++) {
            int fi = tid + 256 * it;
            int r = fi >> 3, c4 = fi & 7;
            float4 v = *(const float4*)(W + (size_t)(nBase + r) * K + kt + c4 * 4);
            int sb = r * 36 + c4 * 4;
            sB[sb] = f2tf(v.x); sB[sb + 1] = f2tf(v.y);
            sB[sb + 2] = f2tf(v.z); sB[sb + 3] = f2tf(v.w);
        }
        __syncthreads();

#pragma unroll
        for (int k8 = 0; k8 < 4; k8++) {
            unsigned a[2][4], b[4][2];
#pragma unroll
            for (int tm = 0; tm < 2; tm++) {
                int r0 = warpM + tm * 16 + (lane >> 2);
                int cc = k8 * 8 + (lane & 3);
                a[tm][0] = sA[r0 * 36 + cc];
                a[tm][1] = sA[(r0 + 8) * 36 + cc];
                a[tm][2] = sA[r0 * 36 + cc + 4];
                a[tm][3] = sA[(r0 + 8) * 36 + cc + 4];
            }
#pragma unroll
            for (int tn = 0; tn < 4; tn++) {
                int n0 = warpN + tn * 8 + (lane >> 2);
                int kk = k8 * 8 + (lane & 3);
                b[tn][0] = sB[n0 * 36 + kk];
                b[tn][1] = sB[n0 * 36 + kk + 4];
            }
#pragma unroll
            for (int tm = 0; tm < 2; tm++)
#pragma unroll
                for (int tn = 0; tn < 4; tn++)
                    mma_tf32(c[tm][tn], a[tm], b[tn]);
        }
        __syncthreads();
    }

    // epilogue
#pragma unroll
    for (int tm = 0; tm < 2; tm++) {
        int r0 = mBase + warpM + tm * 16 + (lane >> 2);
        float rs0 = rs ? rs[r0] : 1.f;
        float rs1 = rs ? rs[r0 + 8] : 1.f;
#pragma unroll
        for (int tn = 0; tn < 4; tn++) {
            int c0 = nBase + warpN + tn * 8 + 2 * (lane & 3);
            float b0 = bias[c0], b1 = bias[c0 + 1];
            float2 v0 = make_float2(c[tm][tn][0] + b0 * rs0, c[tm][tn][1] + b1 * rs0);
            float2 v1 = make_float2(c[tm][tn][2] + b0 * rs1, c[tm][tn][3] + b1 * rs1);
            *(float2*)(C + (size_t)r0 * N + c0) = v0;
            *(float2*)(C + (size_t)(r0 + 8) * N + c0) = v1;
        }
    }
}

// ---------------- kernel 5: GRU combine ----------------
__global__ void k_combine(const float* __restrict__ gf, float* __restrict__ out, int B) {
    int idx = blockIdx.x * 256 + threadIdx.x;
    if (idx >= B * DN) return;
    int g = idx >> 8, h = idx & 255;
    const float* gi = g_gi + (size_t)g * (3 * DN);
    const float* gh = g_gh + (size_t)g * (3 * DN);
    float r = 1.f / (1.f + __expf(-(gi[h] + gh[h])));
    float z = 1.f / (1.f + __expf(-(gi[DN + h] + gh[DN + h])));
    float n = tanhf(gi[2 * DN + h] + r * gh[2 * DN + h]);
    out[idx] = (1.f - z) * n + z * gf[idx];
}

// ---------------- launch ----------------
extern "C" void kernel_launch(void* const* d_in, const int* in_sizes, int n_in,
                              void* d_out, int out_size) {
    const float* nf    = (const float*)d_in[0];   // node_feats (N,256)
    const float* gf    = (const float*)d_in[1];   // graph_feats (B,256)
    const void*  seg   = d_in[2];                 // segment_ids (N,) int32 or int64
    const float* W_msg = (const float*)d_in[3];   // (256,256)
    const float* b_msg = (const float*)d_in[4];   // (256,)
    const float* W_l1  = (const float*)d_in[5];   // (10,512)
    const float* b_l1  = (const float*)d_in[6];   // (10,)
    const float* W_l2  = (const float*)d_in[7];   // (1,10)
    const float* b_l2  = (const float*)d_in[8];   // (1,)
    const float* W_ih  = (const float*)d_in[9];   // (768,256)
    const float* W_hh  = (const float*)d_in[10];  // (768,256)
    const float* b_ih  = (const float*)d_in[11];  // (768,)
    const float* b_hh  = (const float*)d_in[12];  // (768,)
    float* out = (float*)d_out;

    int N = in_sizes[2];          // node count
    int B = in_sizes[1] / DN;     // graph count (4096)

    k_offsets<<<(N + 255) / 256, 256>>>(seg, N, B);
    k_u<<<(B + 7) / 8, 256>>>(gf, W_l1, b_l1, B);
    k_main<<<B, 256>>>(nf, W_l1, W_l2, b_l2);
    k_gemm<<<dim3(DN / BN, B / BM), 256>>>(0, nullptr, W_msg, b_msg, B, DN, DN);
    k_gemm<<<dim3(3 * DN / BN, B / BM), 256>>>(1, nullptr, W_ih, b_ih, B, 3 * DN, DN);
    k_gemm<<<dim3(3 * DN / BN, B / BM), 256>>>(2, gf, W_hh, b_hh, B, 3 * DN, DN);
    k_combine<<<(B * DN + 255) / 256, 256>>>(gf, out, B);
}

// round 9
// speedup vs baseline: 1.1587x; 1.1587x over previous
#include <cuda_runtime.h>
#include <math.h>
#include <stdint.h>

#define DN 256          // D_NODE == D_GRAPH
#define DL 10           // D_LOGIT
#define MAXB 4096
#define TILE 64         // nodes per smem tile
#define RS 260          // padded row stride (floats): (4r + c) mod 32 conflict-free
#define NEG_INF (__int_as_float(0xff800000))

// ---------------- device scratch (no allocations allowed) ----------------
__device__ int   g_offsets[MAXB + 1];
__device__ float g_u[MAXB * DL];          // relu(gf) @ W_l1a^T + b_l1
__device__ float g_S[MAXB * DN];          // normalized weighted node sums
__device__ float g_asum[MAXB];            // sum of alpha per graph (1 or 0)
__device__ float g_gi[MAXB * 3 * DN];
__device__ float g_gh[MAXB * 3 * DN];
__device__ float g_Wc[3 * DN * DN];       // W_ih @ W_msg  (768 x 256)
__device__ float g_bc[3 * DN];            // W_ih @ b_msg  (768)

// ---------------- helpers ----------------
__device__ __forceinline__ float leaky(float x) { return x > 0.f ? x : 0.01f * x; }

__device__ __forceinline__ float blockReduceMax(float v, float* sRed) {
    int tid = threadIdx.x, lane = tid & 31, wid = tid >> 5;
#pragma unroll
    for (int o = 16; o > 0; o >>= 1) v = fmaxf(v, __shfl_xor_sync(0xffffffffu, v, o));
    if (lane == 0) sRed[wid] = v;
    __syncthreads();
    if (tid < 32) {
        float t = (lane < 8) ? sRed[lane] : NEG_INF;
#pragma unroll
        for (int o = 4; o > 0; o >>= 1) t = fmaxf(t, __shfl_xor_sync(0xffffffffu, t, o));
        if (lane == 0) sRed[0] = t;
    }
    __syncthreads();
    float r = sRed[0];
    __syncthreads();
    return r;
}

__device__ __forceinline__ float blockReduceSum(float v, float* sRed) {
    int tid = threadIdx.x, lane = tid & 31, wid = tid >> 5;
#pragma unroll
    for (int o = 16; o > 0; o >>= 1) v += __shfl_xor_sync(0xffffffffu, v, o);
    if (lane == 0) sRed[wid] = v;
    __syncthreads();
    if (tid < 32) {
        float t = (lane < 8) ? sRed[lane] : 0.f;
#pragma unroll
        for (int o = 4; o > 0; o >>= 1) t += __shfl_xor_sync(0xffffffffu, t, o);
        if (lane == 0) sRed[0] = t;
    }
    __syncthreads();
    float r = sRed[0];
    __syncthreads();
    return r;
}

__device__ __forceinline__ unsigned f2tf(float f) {
    unsigned u;
    asm("cvt.rna.tf32.f32 %0, %1;" : "=r"(u) : "f"(f));
    return u;
}

__device__ __forceinline__ void mma_tf32(float* c, const unsigned* a, const unsigned* b) {
    asm volatile(
        "mma.sync.aligned.m16n8k8.row.col.f32.tf32.tf32.f32 "
        "{%0,%1,%2,%3},{%4,%5,%6,%7},{%8,%9},{%0,%1,%2,%3};\n"
        : "+f"(c[0]), "+f"(c[1]), "+f"(c[2]), "+f"(c[3])
        : "r"(a[0]), "r"(a[1]), "r"(a[2]), "r"(a[3]), "r"(b[0]), "r"(b[1]));
}

__device__ __forceinline__ uint32_t smem_u32(const void* p) {
    uint32_t a;
    asm("{ .reg .u64 t; cvta.to.shared.u64 t, %1; cvt.u32.u64 %0, t; }" : "=r"(a) : "l"(p));
    return a;
}

__device__ __forceinline__ void mbar_init(uint32_t mbar) {
    asm volatile("mbarrier.init.shared.b64 [%0], 1;" :: "r"(mbar) : "memory");
}
__device__ __forceinline__ void mbar_expect_tx(uint32_t mbar, uint32_t bytes) {
    asm volatile("mbarrier.arrive.expect_tx.shared.b64 _, [%0], %1;"
                 :: "r"(mbar), "r"(bytes) : "memory");
}
__device__ __forceinline__ void mbar_wait(uint32_t mbar, uint32_t parity) {
    asm volatile(
        "{\n\t.reg .pred P;\n"
        "W_%=:\n\t"
        "mbarrier.try_wait.parity.acquire.cta.shared::cta.b64 P, [%0], %1, 0x989680;\n\t"
        "@P bra D_%=;\n\t"
        "bra W_%=;\n"
        "D_%=:\n\t}"
        :: "r"(mbar), "r"(parity) : "memory");
}
__device__ __forceinline__ void bulk_g2s(uint32_t dst, const void* src, uint32_t bytes,
                                         uint32_t mbar) {
    asm volatile(
        "cp.async.bulk.shared::cta.global.mbarrier::complete_tx::bytes [%0], [%1], %2, [%3];"
        :: "r"(dst), "l"(src), "r"(bytes), "r"(mbar) : "memory");
}

// ---------------- kernel 1: segment offsets ----------------
__global__ void k_offsets(const void* seg_raw, int N, int B) {
    int i = blockIdx.x * blockDim.x + threadIdx.x;
    if (i >= N) return;
    const int* s32 = (const int*)seg_raw;
    bool is64 = true;
    if (N >= 3) {
        int oi = ((N - 1) & 1) ? (N - 1) : (N - 2);
        is64 = (s32[oi] == 0);
    }
    int sv, pv;
    if (is64) {
        const long long* s64 = (const long long*)seg_raw;
        sv = (int)s64[i];
        pv = (i == 0) ? -1 : (int)s64[i - 1];
    } else {
        sv = s32[i];
        pv = (i == 0) ? -1 : s32[i - 1];
    }
    for (int g = pv + 1; g <= sv; ++g) g_offsets[g] = i;
    if (i == N - 1) {
        for (int g = sv + 1; g <= B; ++g) g_offsets[g] = N;
    }
}

// ---------------- kernel 2: per-graph u = relu(gf) @ W_l1[:, :256]^T + b_l1 --
__global__ __launch_bounds__(256) void k_u(const float* __restrict__ gf,
                                           const float* __restrict__ W_l1,
                                           const float* __restrict__ b_l1, int B) {
    __shared__ float sW[DL * DN];
    int tid = threadIdx.x;
    for (int idx = tid; idx < DL * DN; idx += 256) {
        int j = idx / DN, c = idx % DN;
        sW[idx] = W_l1[j * (2 * DN) + c];
    }
    __syncthreads();
    int wid = tid >> 5, lane = tid & 31;
    int g = blockIdx.x * 8 + wid;
    if (g >= B) return;
    float acc[DL];
#pragma unroll
    for (int j = 0; j < DL; j++) acc[j] = 0.f;
    const float4* grow = (const float4*)(gf + (size_t)g * DN);
#pragma unroll
    for (int k2 = 0; k2 < 2; k2++) {
        float4 x = grow[lane + 32 * k2];
        x.x = fmaxf(x.x, 0.f); x.y = fmaxf(x.y, 0.f);
        x.z = fmaxf(x.z, 0.f); x.w = fmaxf(x.w, 0.f);
        int cb = (lane + 32 * k2) * 4;
#pragma unroll
        for (int j = 0; j < DL; j++) {
            float4 w = *(const float4*)&sW[j * DN + cb];
            acc[j] += x.x * w.x + x.y * w.y + x.z * w.z + x.w * w.w;
        }
    }
#pragma unroll
    for (int j = 0; j < DL; j++) {
        float v = acc[j];
#pragma unroll
        for (int o = 16; o > 0; o >>= 1) v += __shfl_xor_sync(0xffffffffu, v, o);
        acc[j] = v;
    }
    if (lane == 0) {
#pragma unroll
        for (int j = 0; j < DL; j++) g_u[g * DL + j] = acc[j] + b_l1[j];
    }
}

// ---------------- kernel 3: fused main pass (single DRAM read of node_feats) -
// smem float layout:
//   sX   [2][TILE*RS]   0      .. 33280
//   sW   [16*RS]        33280  .. 37440   (W_l1b, rows >=10 zero, tf32-rounded)
//   sU   [16]           37440
//   sW2  [16]           37456
//   sPart[64*2]         37472
//   sLog [64]           37600
//   sRed [8]            37664
//   total floats 37672 -> 150688 bytes; mbarriers at byte 150688, 150696
#define SM_FLOATS 37672
#define SMEM_MAIN (SM_FLOATS * 4 + 16)

__global__ __launch_bounds__(256) void k_main(const float* __restrict__ nf,
                                              const float* __restrict__ W_l1,
                                              const float* __restrict__ W_l2,
                                              const float* __restrict__ b_l2) {
    extern __shared__ float sm[];
    float* sX    = sm;
    float* sW    = sm + 2 * TILE * RS;
    float* sU    = sW + 16 * RS;
    float* sW2   = sU + 16;
    float* sPart = sW2 + 16;
    float* sLog  = sPart + 128;
    float* sRed  = sLog + 64;

    uint32_t smb = smem_u32(sm);
    uint32_t mb[2];
    mb[0] = smb + SM_FLOATS * 4;
    mb[1] = mb[0] + 8;

    int tid = threadIdx.x, lane = tid & 31, wid = tid >> 5;
    int g = blockIdx.x;

    // stage W_l1b (node half) as tf32-rounded floats, rows 10..15 zeroed
    for (int idx = tid; idx < 16 * DN; idx += 256) {
        int j = idx >> 8, c = idx & 255;
        float w = (j < DL) ? W_l1[j * (2 * DN) + DN + c] : 0.f;
        sW[j * RS + c] = __uint_as_float(f2tf(w));
    }
    if (tid < 16) {
        sU[tid]  = (tid < DL) ? g_u[g * DL + tid] : 0.f;
        sW2[tid] = (tid < DL) ? W_l2[tid] : 0.f;
    }
    float b2v = __ldg(b_l2);
    int start = g_offsets[g];
    int cnt = g_offsets[g + 1] - start;
    int nt = (cnt + TILE - 1) / TILE;

    if (tid == 0) {
        mbar_init(mb[0]);
        mbar_init(mb[1]);
        asm volatile("fence.proxy.async.shared::cta;" ::: "memory");
    }
    __syncthreads();

    float M = NEG_INF, D = 0.f, Sacc = 0.f;
    int ph0 = 0, ph1 = 0;

    if (nt > 0) {
        // prefetch tile 0 into buffer 0
        int rows0 = min(TILE, cnt);
        if (tid == 0) mbar_expect_tx(mb[0], (uint32_t)rows0 * 1024u);
        __syncthreads();
        if (tid < rows0)
            bulk_g2s(smb + (uint32_t)(tid * RS) * 4u,
                     nf + (size_t)(start + tid) * DN, 1024u, mb[0]);
    }

    for (int t = 0; t < nt; t++) {
        int buf = t & 1;
        int cn = min(TILE, cnt - t * TILE);

        // prefetch tile t+1 into the other buffer (its last reader finished
        // before the __syncthreads below)
        if (t + 1 < nt) {
            int rn = min(TILE, cnt - (t + 1) * TILE);
            if (tid == 0) mbar_expect_tx(mb[buf ^ 1], (uint32_t)rn * 1024u);
            __syncthreads();
            if (tid < rn)
                bulk_g2s(smb + (uint32_t)(((buf ^ 1) * TILE + tid) * RS) * 4u,
                         nf + (size_t)(start + (t + 1) * TILE + tid) * DN,
                         1024u, mb[buf ^ 1]);
        }

        // wait for current tile
        if (buf == 0) { mbar_wait(mb[0], ph0); ph0 ^= 1; }
        else          { mbar_wait(mb[1], ph1); ph1 ^= 1; }

        const float* Xb = sX + buf * TILE * RS;

        // ---- phase 1: logits via tf32 mma: H(64x16) = X(64x256) @ W^T ----
        {
            int mt = wid & 3, ntl = wid >> 2;
            int m0 = mt * 16, n0 = ntl * 8;
            int r = lane >> 2, q = lane & 3;
            const float* aP0 = Xb + (m0 + r) * RS + q;
            const float* aP1 = aP0 + 8 * RS;
            const float* bP  = sW + (n0 + r) * RS + q;
            float c[4] = {0.f, 0.f, 0.f, 0.f};
#pragma unroll
            for (int k8 = 0; k8 < 32; k8++) {
                int kk = k8 * 8;
                unsigned a[4], b[2];
                a[0] = __float_as_uint(aP0[kk]);
                a[1] = __float_as_uint(aP1[kk]);
                a[2] = __float_as_uint(aP0[kk + 4]);
                a[3] = __float_as_uint(aP1[kk + 4]);
                b[0] = __float_as_uint(bP[kk]);
                b[1] = __float_as_uint(bP[kk + 4]);
                mma_tf32(c, a, b);
            }
            // inner leaky + W2 partial dot (cols n0+2q, n0+2q+1)
            int c0i = n0 + 2 * q, c1i = c0i + 1;
            float uA = sU[c0i], uB = sU[c1i], wA = sW2[c0i], wB = sW2[c1i];
            float p0 = leaky(c[0] + uA) * wA + leaky(c[1] + uB) * wB;
            float p1 = leaky(c[2] + uA) * wA + leaky(c[3] + uB) * wB;
            p0 += __shfl_xor_sync(0xffffffffu, p0, 1);
            p0 += __shfl_xor_sync(0xffffffffu, p0, 2);
            p1 += __shfl_xor_sync(0xffffffffu, p1, 1);
            p1 += __shfl_xor_sync(0xffffffffu, p1, 2);
            if (q == 0) {
                sPart[(m0 + r) * 2 + ntl]     = p0;
                sPart[(m0 + r + 8) * 2 + ntl] = p1;
            }
        }
        __syncthreads();

        if (tid < TILE)
            sLog[tid] = leaky(b2v + sPart[tid * 2] + sPart[tid * 2 + 1]);
        // (each thread below reads only its own sLog entry before the
        //  reductions; reductions contain __syncthreads)

        // ---- online softmax update ----
        float lv = (tid < cn) ? sLog[tid] : NEG_INF;
        float mc = blockReduceMax(lv, sRed);
        float Mn = fmaxf(M, mc);
        float scale = (M == NEG_INF) ? 0.f : __expf(M - Mn);
        float w = 0.f;
        if (tid < cn) {
            w = __expf(sLog[tid] - Mn);
            sLog[tid] = w;
        }
        float dc = blockReduceSum(w, sRed);
        D = D * scale + dc;
        M = Mn;

        // ---- phase 2: weighted column accumulation from smem ----
        Sacc *= scale;
        const float* Xc = Xb + tid;
#pragma unroll 4
        for (int n = 0; n < cn; n++) Sacc = fmaf(sLog[n], Xc[n * RS], Sacc);
        __syncthreads();  // done with sLog + this buffer
    }

    float inv = 1.f / fmaxf(D, 1e-30f);
    g_S[(size_t)g * DN + tid] = (cnt > 0) ? Sacc * inv : 0.f;
    if (tid == 0) g_asum[g] = (cnt > 0) ? 1.f : 0.f;
}

// ---------------- kernel: fold W_ih @ W_msg and W_ih @ b_msg ----------------
__global__ __launch_bounds__(256) void k_prep(const float* __restrict__ W_ih,
                                              const float* __restrict__ W_msg,
                                              const float* __restrict__ b_msg) {
    __shared__ float sT[256 * 20];  // transposed 16 rows of W_ih, stride 20
    __shared__ float sb[256];
    int i0 = blockIdx.x * 16;
    int tid = threadIdx.x;
    for (int idx = tid; idx < 16 * 256; idx += 256) {
        int i = idx >> 8, m = idx & 255;
        sT[m * 20 + i] = W_ih[(size_t)(i0 + i) * 256 + m];
    }
    sb[tid] = b_msg[tid];
    __syncthreads();

    float acc[16];
#pragma unroll
    for (int i = 0; i < 16; i++) acc[i] = 0.f;
    int j = tid;
#pragma unroll 4
    for (int m = 0; m < 256; m++) {
        float wm = W_msg[(size_t)m * 256 + j];
        const float4* tp = (const float4*)&sT[m * 20];
        float4 t0 = tp[0], t1 = tp[1], t2 = tp[2], t3 = tp[3];
        acc[0]  = fmaf(wm, t0.x, acc[0]);  acc[1]  = fmaf(wm, t0.y, acc[1]);
        acc[2]  = fmaf(wm, t0.z, acc[2]);  acc[3]  = fmaf(wm, t0.w, acc[3]);
        acc[4]  = fmaf(wm, t1.x, acc[4]);  acc[5]  = fmaf(wm, t1.y, acc[5]);
        acc[6]  = fmaf(wm, t1.z, acc[6]);  acc[7]  = fmaf(wm, t1.w, acc[7]);
        acc[8]  = fmaf(wm, t2.x, acc[8]);  acc[9]  = fmaf(wm, t2.y, acc[9]);
        acc[10] = fmaf(wm, t2.z, acc[10]); acc[11] = fmaf(wm, t2.w, acc[11]);
        acc[12] = fmaf(wm, t3.x, acc[12]); acc[13] = fmaf(wm, t3.y, acc[13]);
        acc[14] = fmaf(wm, t3.z, acc[14]); acc[15] = fmaf(wm, t3.w, acc[15]);
    }
#pragma unroll
    for (int i = 0; i < 16; i++) g_Wc[(size_t)(i0 + i) * 256 + j] = acc[i];

    if (tid < 16) {
        float s = 0.f;
        for (int m = 0; m < 256; m++) s = fmaf(sT[m * 20 + tid], sb[m], s);
        g_bc[i0 + tid] = s;
    }
}

// ---------------- kernel 4: merged tf32 GEMM for gi and gh ----------------
// gi = g_S @ g_Wc^T + b_ih + asum * g_bc     (blockIdx.x <  12)
// gh = gf  @ W_hh^T + b_hh                   (blockIdx.x >= 12)
#define BM 128
#define BN 64
#define BK 32

__global__ __launch_bounds__(256) void k_gemm2(const float* __restrict__ gf,
                                               const float* __restrict__ W_hh,
                                               const float* __restrict__ b_hh,
                                               const float* __restrict__ b_ih) {
    __shared__ unsigned sA[BM * 36];
    __shared__ unsigned sB[BN * 36];

    bool is_gi = blockIdx.x < 12;
    const float* A = is_gi ? g_S : gf;
    const float* W = is_gi ? g_Wc : W_hh;
    float* C = is_gi ? g_gi : g_gh;
    const float* b1 = is_gi ? b_ih : b_hh;
    const int N = 3 * DN, K = DN;

    int tid = threadIdx.x, lane = tid & 31, wid = tid >> 5;
    int nBase = (blockIdx.x % 12) * BN, mBase = blockIdx.y * BM;
    int warpM = (wid & 3) * 32, warpN = (wid >> 2) * 32;

    float c[2][4][4];
#pragma unroll
    for (int tm = 0; tm < 2; tm++)
#pragma unroll
        for (int tn = 0; tn < 4; tn++)
#pragma unroll
            for (int q = 0; q < 4; q++) c[tm][tn][q] = 0.f;

    for (int kt = 0; kt < K; kt += BK) {
#pragma unroll
        for (int it = 0; it < 4; it++) {
            int fi = tid + 256 * it;
            int r = fi >> 3, c4 = fi & 7;
            float4 v = *(const float4*)(A + (size_t)(mBase + r) * K + kt + c4 * 4);
            int sa = r * 36 + c4 * 4;
            sA[sa] = f2tf(v.x); sA[sa + 1] = f2tf(v.y);
            sA[sa + 2] = f2tf(v.z); sA[sa + 3] = f2tf(v.w);
        }
#pragma unroll
        for (int it = 0; it < 2; it++) {
            int fi = tid + 256 * it;
            int r = fi >> 3, c4 = fi & 7;
            float4 v = *(const float4*)(W + (size_t)(nBase + r) * K + kt + c4 * 4);
            int sb = r * 36 + c4 * 4;
            sB[sb] = f2tf(v.x); sB[sb + 1] = f2tf(v.y);
            sB[sb + 2] = f2tf(v.z); sB[sb + 3] = f2tf(v.w);
        }
        __syncthreads();

#pragma unroll
        for (int k8 = 0; k8 < 4; k8++) {
            unsigned a[2][4], b[4][2];
#pragma unroll
            for (int tm = 0; tm < 2; tm++) {
                int r0 = warpM + tm * 16 + (lane >> 2);
                int cc = k8 * 8 + (lane & 3);
                a[tm][0] = sA[r0 * 36 + cc];
                a[tm][1] = sA[(r0 + 8) * 36 + cc];
                a[tm][2] = sA[r0 * 36 + cc + 4];
                a[tm][3] = sA[(r0 + 8) * 36 + cc + 4];
            }
#pragma unroll
            for (int tn = 0; tn < 4; tn++) {
                int n0 = warpN + tn * 8 + (lane >> 2);
                int kk = k8 * 8 + (lane & 3);
                b[tn][0] = sB[n0 * 36 + kk];
                b[tn][1] = sB[n0 * 36 + kk + 4];
            }
#pragma unroll
            for (int tm = 0; tm < 2; tm++)
#pragma unroll
                for (int tn = 0; tn < 4; tn++)
                    mma_tf32(c[tm][tn], a[tm], b[tn]);
        }
        __syncthreads();
    }

#pragma unroll
    for (int tm = 0; tm < 2; tm++) {
        int r0 = mBase + warpM + tm * 16 + (lane >> 2);
        float rs0 = is_gi ? g_asum[r0] : 0.f;
        float rs1 = is_gi ? g_asum[r0 + 8] : 0.f;
#pragma unroll
        for (int tn = 0; tn < 4; tn++) {
            int c0 = nBase + warpN + tn * 8 + 2 * (lane & 3);
            float bb0 = b1[c0], bb1 = b1[c0 + 1];
            float e0 = is_gi ? g_bc[c0] : 0.f;
            float e1 = is_gi ? g_bc[c0 + 1] : 0.f;
            float2 v0 = make_float2(c[tm][tn][0] + bb0 + e0 * rs0,
                                    c[tm][tn][1] + bb1 + e1 * rs0);
            float2 v1 = make_float2(c[tm][tn][2] + bb0 + e0 * rs1,
                                    c[tm][tn][3] + bb1 + e1 * rs1);
            *(float2*)(C + (size_t)r0 * N + c0) = v0;
            *(float2*)(C + (size_t)(r0 + 8) * N + c0) = v1;
        }
    }
}

// ---------------- kernel 5: GRU combine ----------------
__global__ void k_combine(const float* __restrict__ gf, float* __restrict__ out, int B) {
    int idx = blockIdx.x * 256 + threadIdx.x;
    if (idx >= B * DN) return;
    int g = idx >> 8, h = idx & 255;
    const float* gi = g_gi + (size_t)g * (3 * DN);
    const float* gh = g_gh + (size_t)g * (3 * DN);
    float r = 1.f / (1.f + __expf(-(gi[h] + gh[h])));
    float z = 1.f / (1.f + __expf(-(gi[DN + h] + gh[DN + h])));
    float n = tanhf(gi[2 * DN + h] + r * gh[2 * DN + h]);
    out[idx] = (1.f - z) * n + z * gf[idx];
}

// ---------------- launch ----------------
extern "C" void kernel_launch(void* const* d_in, const int* in_sizes, int n_in,
                              void* d_out, int out_size) {
    const float* nf    = (const float*)d_in[0];
    const float* gf    = (const float*)d_in[1];
    const void*  seg   = d_in[2];
    const float* W_msg = (const float*)d_in[3];
    const float* b_msg = (const float*)d_in[4];
    const float* W_l1  = (const float*)d_in[5];
    const float* b_l1  = (const float*)d_in[6];
    const float* W_l2  = (const float*)d_in[7];
    const float* b_l2  = (const float*)d_in[8];
    const float* W_ih  = (const float*)d_in[9];
    const float* W_hh  = (const float*)d_in[10];
    const float* b_hh  = (const float*)d_in[12];
    const float* b_ih  = (const float*)d_in[11];
    float* out = (float*)d_out;

    int N = in_sizes[2];
    int B = in_sizes[1] / DN;

    cudaFuncSetAttribute(k_main, cudaFuncAttributeMaxDynamicSharedMemorySize, SMEM_MAIN);

    k_offsets<<<(N + 255) / 256, 256>>>(seg, N, B);
    k_prep<<<48, 256>>>(W_ih, W_msg, b_msg);
    k_u<<<(B + 7) / 8, 256>>>(gf, W_l1, b_l1, B);
    k_main<<<B, 256, SMEM_MAIN>>>(nf, W_l1, W_l2, b_l2);
    k_gemm2<<<dim3(24, B / BM), 256>>>(gf, W_hh, b_hh, b_ih);
    k_combine<<<(B * DN + 255) / 256, 256>>>(gf, out, B);
}